// round 5
// baseline (speedup 1.0000x reference)
#include <cuda_runtime.h>
#include <cuda_bf16.h>

// TopDownProjector: for each column [b,c,y,x,:] (D=256 contiguous fp32),
// scan from depth D-1 downward for the first non-zero voxel.
//   out[0 .. N)   = height_field (depth index of hit, 0 if empty)
//   out[N .. 2N)  = seg_map (voxel value at hit, 0 if empty)
//
// Roofline analysis (R1-R4): warm runs move 67.5 MB of mandatory 128B line
// fills (one line per column) at ~8.2 TB/s -> we are at the HBM roofline.
// This round: R2's optimal geometry (4 cols/thread, MLP=4, 512x256) plus
// streaming output stores (evict-first) so the 4.2 MB of outputs don't
// displace volume lines from L2 between graph replays.

static constexpr int D = 256;

__device__ __forceinline__ float2 resolve_col(const float* __restrict__ colp,
                                              float4 v) {
    int base = D - 4;
    for (;;) {
        if (v.w != 0.0f) return make_float2((float)(base + 3), v.w);
        if (v.z != 0.0f) return make_float2((float)(base + 2), v.z);
        if (v.y != 0.0f) return make_float2((float)(base + 1), v.y);
        if (v.x != 0.0f) return make_float2((float)(base + 0), v.x);
        base -= 4;
        if (base < 0) return make_float2(0.0f, 0.0f);
        v = *reinterpret_cast<const float4*>(colp + base);
    }
}

__global__ void __launch_bounds__(256)
topdown_kernel4(const float* __restrict__ volume,
                float4* __restrict__ height4,
                float4* __restrict__ seg4,
                int n_quads) {
    int q = blockIdx.x * blockDim.x + threadIdx.x;
    if (q >= n_quads) return;

    const float* p0 = volume + ((size_t)q * 4 + 0) * D;
    const float* p1 = volume + ((size_t)q * 4 + 1) * D;
    const float* p2 = volume + ((size_t)q * 4 + 2) * D;
    const float* p3 = volume + ((size_t)q * 4 + 3) * D;

    // Four independent top loads (MLP=4), read-only path.
    float4 v0 = __ldg(reinterpret_cast<const float4*>(p0 + (D - 4)));
    float4 v1 = __ldg(reinterpret_cast<const float4*>(p1 + (D - 4)));
    float4 v2 = __ldg(reinterpret_cast<const float4*>(p2 + (D - 4)));
    float4 v3 = __ldg(reinterpret_cast<const float4*>(p3 + (D - 4)));

    float2 r0 = resolve_col(p0, v0);
    float2 r1 = resolve_col(p1, v1);
    float2 r2 = resolve_col(p2, v2);
    float2 r3 = resolve_col(p3, v3);

    // Streaming (evict-first) coalesced stores: outputs are write-once and
    // read by the host; don't let them displace volume lines in L2.
    __stcs(height4 + q, make_float4(r0.x, r1.x, r2.x, r3.x));
    __stcs(seg4 + q,    make_float4(r0.y, r1.y, r2.y, r3.y));
}

extern "C" void kernel_launch(void* const* d_in, const int* in_sizes, int n_in,
                              void* d_out, int out_size) {
    const float* volume = (const float*)d_in[0];
    float* out = (float*)d_out;

    int n_cols  = in_sizes[0] / D;     // 524288 for [2,1,512,512,256]
    int n_quads = n_cols / 4;

    float4* height4 = (float4*)out;
    float4* seg4    = (float4*)(out + n_cols);

    int threads = 256;
    int blocks = (n_quads + threads - 1) / threads;   // 512 blocks
    topdown_kernel4<<<blocks, threads>>>(volume, height4, seg4, n_quads);
}

// round 7
// speedup vs baseline: 1.0370x; 1.0370x over previous
#include <cuda_runtime.h>
#include <cuda_bf16.h>
#include <cstdint>

// TopDownProjector: for each column [b,c,y,x,:] (D=256 contiguous fp32),
// scan from depth D-1 downward for the first non-zero voxel.
//   out[0 .. N)   = height_field (depth index of hit, 0 if empty)
//   out[N .. 2N)  = seg_map (voxel value at hit, 0 if empty)
//
// Warm-path model: replays hit L2 for ~50% of the 67.5 MB touched-line
// footprint. Pin gather lines with ld.global.nc.L2::evict_last.v4.b64
// (32B = top 8 voxels per column; ptxas requires v4.b64 for this modifier).
// p(unresolved by top 8) = (1/9)^8 ~ 2e-8 -> scalar descent fallback.

static constexpr int D = 256;

struct Top8 { float f[8]; };   // depths D-8 .. D-1

__device__ __forceinline__ Top8 ld_top8_persist(const float* p /* colp + D-8 */) {
    uint64_t a, b, c, d;
    asm volatile("ld.global.nc.L2::evict_last.v4.b64 {%0,%1,%2,%3}, [%4];"
                 : "=l"(a), "=l"(b), "=l"(c), "=l"(d)
                 : "l"(p));
    Top8 t;
    t.f[0] = __uint_as_float((uint32_t)a);  t.f[1] = __uint_as_float((uint32_t)(a >> 32));
    t.f[2] = __uint_as_float((uint32_t)b);  t.f[3] = __uint_as_float((uint32_t)(b >> 32));
    t.f[4] = __uint_as_float((uint32_t)c);  t.f[5] = __uint_as_float((uint32_t)(c >> 32));
    t.f[6] = __uint_as_float((uint32_t)d);  t.f[7] = __uint_as_float((uint32_t)(d >> 32));
    return t;
}

__device__ __forceinline__ float2 resolve_col(const float* __restrict__ colp,
                                              const Top8& t) {
    #pragma unroll
    for (int i = 7; i >= 0; --i)
        if (t.f[i] != 0.0f)
            return make_float2((float)(D - 8 + i), t.f[i]);
    // ~2e-8 per column: scan the rest from global (scalar descent).
    for (int k = D - 9; k >= 0; --k) {
        float v = __ldg(colp + k);
        if (v != 0.0f) return make_float2((float)k, v);
    }
    return make_float2(0.0f, 0.0f);
}

__global__ void __launch_bounds__(256)
topdown_kernel4(const float* __restrict__ volume,
                float4* __restrict__ height4,
                float4* __restrict__ seg4,
                int n_quads) {
    int q = blockIdx.x * blockDim.x + threadIdx.x;
    if (q >= n_quads) return;

    const float* p0 = volume + ((size_t)q * 4 + 0) * D;
    const float* p1 = volume + ((size_t)q * 4 + 1) * D;
    const float* p2 = volume + ((size_t)q * 4 + 2) * D;
    const float* p3 = volume + ((size_t)q * 4 + 3) * D;

    // Four independent 32B persisting top loads (MLP=4).
    Top8 t0 = ld_top8_persist(p0 + (D - 8));
    Top8 t1 = ld_top8_persist(p1 + (D - 8));
    Top8 t2 = ld_top8_persist(p2 + (D - 8));
    Top8 t3 = ld_top8_persist(p3 + (D - 8));

    float2 r0 = resolve_col(p0, t0);
    float2 r1 = resolve_col(p1, t1);
    float2 r2 = resolve_col(p2, t2);
    float2 r3 = resolve_col(p3, t3);

    height4[q] = make_float4(r0.x, r1.x, r2.x, r3.x);
    seg4[q]    = make_float4(r0.y, r1.y, r2.y, r3.y);
}

extern "C" void kernel_launch(void* const* d_in, const int* in_sizes, int n_in,
                              void* d_out, int out_size) {
    const float* volume = (const float*)d_in[0];
    float* out = (float*)d_out;

    int n_cols  = in_sizes[0] / D;     // 524288 for [2,1,512,512,256]
    int n_quads = n_cols / 4;

    float4* height4 = (float4*)out;
    float4* seg4    = (float4*)(out + n_cols);

    int threads = 256;
    int blocks = (n_quads + threads - 1) / threads;   // 512 blocks
    topdown_kernel4<<<blocks, threads>>>(volume, height4, seg4, n_quads);
}